// round 15
// baseline (speedup 1.0000x reference)
#include <cuda_runtime.h>
#include <math.h>
#include <stdint.h>

// Problem constants
#define H    2048
#define E    8
#define I16  16
#define NTOK 8192
#define NB   64            // bucket ids lo*8+hi (28 valid)
#define TB   32            // tokens per tile (2 CTAs/SM)
#define KC   128           // k-chunk (phase A)
#define NCH  (H / KC)      // 16
#define XP   132           // X/D row pitch (floats)
#define AIP  36            // As pitch over i
#define UPB  264           // Uc row pitch (floats)
#define GRID 296           // 2 CTAs x 148 SMs = one resident wave

// smem layout (float offsets): 3 XD buffers; 3 U buffers overlap XD region
#define XDSZ    (64 * XP)               // one X+D buffer: 8448 floats
#define USZ     (32 * UPB)              // one Uc buffer: 8448 floats
#define AS_OFF  (3 * XDSZ)              // 25344
#define RED_OFF (AS_OFF + TB * AIP)     // 26496
#define SM_FLOATS (RED_OFF + 1024)      // 27520 floats = 110080 B

#define XD_BYTES (64 * 512)             // bulk tx per phase-A chunk
#define U_BYTES  (32 * 1024)            // bulk tx per phase-B pass

// f32x2 helpers (router)
#define FMA2(d, a, b) asm("fma.rn.f32x2 %0, %1, %2, %0;" : "+l"(d) : "l"(a), "l"(b))
#define UNPACK2(lo, hi, d) asm("mov.b64 {%0, %1}, %2;" : "=f"(lo), "=f"(hi) : "l"(d))

__device__ __forceinline__ unsigned su32(const void* p) {
    return (unsigned)__cvta_generic_to_shared(p);
}

// ---- bulk-copy + mbarrier primitives ----
#define MBAR_INIT(addr, cnt) \
    asm volatile("mbarrier.init.shared.b64 [%0], %1;" :: "r"(addr), "r"(cnt) : "memory")
#define MBAR_EXPECT(addr, tx) \
    asm volatile("mbarrier.arrive.expect_tx.shared.b64 _, [%0], %1;" :: "r"(addr), "r"(tx) : "memory")
#define BULK_G2S(dst, src, bytes, mbar) \
    asm volatile("cp.async.bulk.shared::cta.global.mbarrier::complete_tx::bytes [%0], [%1], %2, [%3];" \
                 :: "r"(dst), "l"(src), "r"(bytes), "r"(mbar) : "memory")

__device__ __forceinline__ void mbar_wait(unsigned mbar, unsigned parity) {
    asm volatile(
        "{\n\t"
        ".reg .pred P1;\n\t"
        "LAB_WAIT_%=:\n\t"
        "mbarrier.try_wait.parity.acquire.cta.shared::cta.b64 P1, [%0], %1, 0x989680;\n\t"
        "@P1 bra.uni LAB_DONE_%=;\n\t"
        "bra.uni LAB_WAIT_%=;\n\t"
        "LAB_DONE_%=:\n\t"
        "}"
        :: "r"(mbar), "r"(parity) : "memory");
}

__device__ __forceinline__ uint32_t cvt_tf32(float f) {
    uint32_t r;
    asm("cvt.rna.tf32.f32 %0, %1;" : "=r"(r) : "f"(f));
    return r;
}

__device__ __forceinline__ void mma_tf32(float d[4],
                                         uint32_t a0, uint32_t a1, uint32_t a2, uint32_t a3,
                                         uint32_t b0, uint32_t b1) {
    asm volatile(
        "mma.sync.aligned.m16n8k8.row.col.f32.tf32.tf32.f32 "
        "{%0,%1,%2,%3}, {%4,%5,%6,%7}, {%8,%9}, {%0,%1,%2,%3};"
        : "+f"(d[0]), "+f"(d[1]), "+f"(d[2]), "+f"(d[3])
        : "r"(a0), "r"(a1), "r"(a2), "r"(a3), "r"(b0), "r"(b1));
}

// ---------------- device scratch (zero-initialized at load) ----------------
__device__ int      g_count[NB];
__device__ int      g_done1;
__device__ int      g_done2;
__device__ int      g_tok[NB][NTOK];
__device__ float2   g_gate[NB][NTOK];
__device__ float    g_dwc[E * I16 * H];   // dw, tf32-rounded, layout [e][i][h]
__device__ float    g_ut[E * I16 * H];    // uw transposed+rounded: [e][i][h]

// ---------------- fused kernel: prep + router -> grid barrier -> expert ----
__global__ __launch_bounds__(256, 2)
void fused_kernel(const float* __restrict__ x,  const float* __restrict__ rw,
                  const float* __restrict__ dw, const float* __restrict__ uw,
                  float* __restrict__ out) {
    extern __shared__ float sm[];
    float* As  = sm + AS_OFF;
    float* Red = sm + RED_OFF;

    __shared__ int    pref[NB + 1];
    __shared__ int    Ts[TB];
    __shared__ float2 Gs[TB];
    __shared__ __align__(8) unsigned long long mbars[3];

    const int tid = threadIdx.x;
    const int w = tid >> 5;
    const int l = tid & 31;

    // ================= Part 0: weight prep (strided over grid) =============
    for (int idx = blockIdx.x * 256 + tid; idx < 65536; idx += gridDim.x * 256) {
        float4 v = ((const float4*)dw)[idx];
        float4 o;
        *(uint32_t*)&o.x = cvt_tf32(v.x);
        *(uint32_t*)&o.y = cvt_tf32(v.y);
        *(uint32_t*)&o.z = cvt_tf32(v.z);
        *(uint32_t*)&o.w = cvt_tf32(v.w);
        ((float4*)g_dwc)[idx] = o;

        float4 u = ((const float4*)uw)[idx];
        int e  = idx >> 13;
        int rm = idx & 8191;
        int h  = rm >> 2;
        int iq = (rm & 3) * 4;
        uint32_t* utb = (uint32_t*)(g_ut + (size_t)(e * I16) * H + h);
        utb[(iq + 0) * H] = cvt_tf32(u.x);
        utb[(iq + 1) * H] = cvt_tf32(u.y);
        utb[(iq + 2) * H] = cvt_tf32(u.z);
        utb[(iq + 3) * H] = cvt_tf32(u.w);
    }

    // ================= Part 1: router (4 tokens per warp) ===================
    {
        const int wg = blockIdx.x * 8 + w;           // global warp id
        if (wg < NTOK / 4) {
            const int t0 = wg * 4;

            unsigned long long acc[E][4];
#pragma unroll
            for (int e = 0; e < E; e++)
#pragma unroll
                for (int j = 0; j < 4; j++) acc[e][j] = 0ull;

#pragma unroll 2
            for (int s = 0; s < 16; s++) {
                ulonglong2 xv[4];
#pragma unroll
                for (int j = 0; j < 4; j++)
                    xv[j] = ((const ulonglong2*)(x + (size_t)(t0 + j) * H))[l + 32 * s];
#pragma unroll
                for (int e = 0; e < E; e++) {
                    ulonglong2 wv = ((const ulonglong2*)(rw + e * H))[l + 32 * s];
#pragma unroll
                    for (int j = 0; j < 4; j++) {
                        FMA2(acc[e][j], xv[j].x, wv.x);
                        FMA2(acc[e][j], xv[j].y, wv.y);
                    }
                }
            }

            float lg[E];
#pragma unroll
            for (int e = 0; e < E; e++) {
#pragma unroll
                for (int j = 0; j < 4; j++) {
                    float s0, s1;
                    UNPACK2(s0, s1, acc[e][j]);
                    float v = s0 + s1;
#pragma unroll
                    for (int o = 16; o > 0; o >>= 1) v += __shfl_xor_sync(0xffffffffu, v, o);
                    if (l == j) lg[e] = v;
                }
            }

            if (l < 4) {
                int t = t0 + l;
                float m = lg[0];
#pragma unroll
                for (int e = 1; e < E; e++) m = fmaxf(m, lg[e]);
                float wgt[E]; float ssum = 0.f;
#pragma unroll
                for (int e = 0; e < E; e++) { wgt[e] = __expf(lg[e] - m); ssum += wgt[e]; }
                float inv = 1.f / ssum;

                int i1 = 0; float v1 = wgt[0];
#pragma unroll
                for (int e = 1; e < E; e++) if (wgt[e] > v1) { v1 = wgt[e]; i1 = e; }
                int i2 = -1; float v2 = -1.f;
#pragma unroll
                for (int e = 0; e < E; e++)
                    if (e != i1 && wgt[e] > v2) { v2 = wgt[e]; i2 = e; }

                float g1 = v1 * inv, g2 = v2 * inv;
                int lo, hi; float glo, ghi;
                if (i1 < i2) { lo = i1; hi = i2; glo = g1; ghi = g2; }
                else         { lo = i2; hi = i1; glo = g2; ghi = g1; }
                int p = lo * 8 + hi;
                int slot = atomicAdd(&g_count[p], 1);
                g_tok[p][slot]  = t;
                g_gate[p][slot] = make_float2(glo, ghi);
            }
        }
    }

    // ================= Grid barrier #1 (all routing + prep done) ============
    __syncthreads();
    if (tid == 0) {
        __threadfence();
        atomicAdd(&g_done1, 1);
        while (atomicAdd(&g_done1, 0) < (int)gridDim.x) { }
        __threadfence();
    }
    __syncthreads();

    // ================= Part 2: expert compute (R14 structure) ===============
    const int gp  = l >> 2;          // group id (0..7)
    const int tg4 = l & 3;           // thread in group
    const int kg = w >> 2;           // phase A split-K group (0..1)
    const int wl = w & 3;
    const int mw = wl & 1;           // phase A token block (16 tok)
    const int nw = wl >> 1;          // phase A i block (16 i)
    const int m2 = w & 1;            // phase B token half
    const int nh = w >> 1;           // phase B h quarter (64 h)

    const unsigned mb0 = su32(&mbars[0]);
    const unsigned mb1 = su32(&mbars[1]);
    const unsigned mb2 = su32(&mbars[2]);
    int ph0 = 0, ph1 = 0, ph2 = 0;

    if (tid == 0) { MBAR_INIT(mb0, 1); MBAR_INIT(mb1, 1); MBAR_INIT(mb2, 1); }

    auto waitbuf = [&](int bb) {
        if (bb == 0)      { mbar_wait(mb0, ph0); ph0 ^= 1; }
        else if (bb == 1) { mbar_wait(mb1, ph1); ph1 ^= 1; }
        else              { mbar_wait(mb2, ph2); ph2 ^= 1; }
    };

    // flat tile prefix
    if (tid < NB) {
        int lo_ = tid >> 3, hi_ = tid & 7;
        pref[tid + 1] = (lo_ < hi_) ? (g_count[tid] + TB - 1) / TB : 0;
    }
    __syncthreads();
    if (tid == 0) {
        int s = 0;
        pref[0] = 0;
        for (int i = 1; i <= NB; i++) { s += pref[i]; pref[i] = s; }
    }
    __syncthreads();
    const int ntiles = pref[NB];

    for (int ft = blockIdx.x; ft < ntiles; ft += gridDim.x) {
        int a = 0, b = NB;
        while (b - a > 1) { int mM = (a + b) >> 1; if (pref[mM] <= ft) a = mM; else b = mM; }
        const int p  = a;
        const int lo = p >> 3, hi = p & 7;
        const int cnt  = g_count[p];
        const int base = (ft - pref[p]) * TB;
        const int n    = min(TB, cnt - base);

        __syncthreads();
        if (tid < TB) {
            int src = base + ((tid < n) ? tid : 0);
            Ts[tid] = g_tok[p][src];
            float2 gg = g_gate[p][src];
            if (tid >= n) gg = make_float2(0.f, 0.f);
            Gs[tid] = gg;
        }
        __syncthreads();

        // ---------------- Phase A ----------------
        float d[2][4];
#pragma unroll
        for (int t = 0; t < 2; t++)
#pragma unroll
            for (int q = 0; q < 4; q++) d[t][q] = 0.f;

        auto stage = [&](int c, int bb) {
            unsigned mb = (bb == 0) ? mb0 : (bb == 1) ? mb1 : mb2;
            if (tid == 0) MBAR_EXPECT(mb, XD_BYTES);
            if (tid < 32) {
                unsigned dst = su32(sm + bb * XDSZ + tid * XP);
                BULK_G2S(dst, x + (size_t)Ts[tid] * H + c * KC, 512, mb);
            } else if (tid < 64) {
                int r = tid - 32;
                int e = (r < 16) ? lo : hi;
                unsigned dst = su32(sm + bb * XDSZ + (32 + r) * XP);
                BULK_G2S(dst, g_dwc + (size_t)(e * I16 + (r & 15)) * H + c * KC, 512, mb);
            }
        };

        stage(0, 0);
        stage(1, 1);

        const int xr0 = (16 * mw + gp) * XP;
        const int xr1 = xr0 + 8 * XP;
        const int dr0 = (32 + 16 * nw + gp) * XP;
        const int dr1 = dr0 + 8 * XP;

        for (int c = 0; c < NCH; c++) {
            const int bb = c % 3;
            waitbuf(bb);
            __syncthreads();
            if (c + 2 < NCH) stage(c + 2, (c + 2) % 3);

            const float*    Xb = sm + bb * XDSZ;
            const uint32_t* Db = (const uint32_t*)Xb;
#pragma unroll
            for (int si = 0; si < 8; si++) {
                const int ca = 8 * (8 * kg + si) + tg4;
                uint32_t a0 = cvt_tf32(Xb[xr0 + ca]);
                uint32_t a1 = cvt_tf32(Xb[xr1 + ca]);
                uint32_t a2 = cvt_tf32(Xb[xr0 + ca + 4]);
                uint32_t a3 = cvt_tf32(Xb[xr1 + ca + 4]);
                uint32_t b00 = Db[dr0 + ca];
                uint32_t b01 = Db[dr0 + ca + 4];
                uint32_t b10 = Db[dr1 + ca];
                uint32_t b11 = Db[dr1 + ca + 4];
                mma_tf32(d[0], a0, a1, a2, a3, b00, b01);
                mma_tf32(d[1], a0, a1, a2, a3, b10, b11);
            }
        }

        // split-K reduce: kg==1 writes partials to Red
        if (kg == 1) {
            float* rp = Red + wl * 256 + l * 8;
            *(float4*)(rp)     = make_float4(d[0][0], d[0][1], d[0][2], d[0][3]);
            *(float4*)(rp + 4) = make_float4(d[1][0], d[1][1], d[1][2], d[1][3]);
        }
        __syncthreads();

        if (kg == 0) {
            const float* rp = Red + wl * 256 + l * 8;
            int r0 = 16 * mw + gp, r1 = r0 + 8;
            float2 gg0 = Gs[r0], gg1 = Gs[r1];
            float gt0 = nw ? gg0.y : gg0.x;
            float gt1 = nw ? gg1.y : gg1.x;
#pragma unroll
            for (int t = 0; t < 2; t++) {
                int cbase = 16 * nw + 8 * t + 2 * tg4;
#pragma unroll
                for (int q = 0; q < 4; q++) {
                    float hv = d[t][q] + rp[t * 4 + q];
                    float sig = 1.f / (1.f + __expf(-hv));
                    float gate = (q < 2) ? gt0 : gt1;
                    float val = gate * hv * sig;
                    int row = (q < 2) ? r0 : r1;
                    int col = cbase + (q & 1);
                    *(uint32_t*)&As[row * AIP + col] = cvt_tf32(val);
                }
            }
        }
        __syncthreads();             // As ready; XD region free for Uc

        // ---------------- Phase B ----------------
        auto stage_u = [&](int pp, int bb) {
            unsigned mb = (bb == 0) ? mb0 : (bb == 1) ? mb1 : mb2;
            if (tid == 0) MBAR_EXPECT(mb, U_BYTES);
            if (tid < 32) {
                int e = (tid < 16) ? lo : hi;
                unsigned dst = su32(sm + bb * USZ + tid * UPB);
                BULK_G2S(dst, g_ut + (size_t)(e * I16 + (tid & 15)) * H + pp * 256, 1024, mb);
            }
        };

        stage_u(0, 0);
        stage_u(1, 1);

        uint32_t pa[4][4];
        {
            const uint32_t* Au = (const uint32_t*)As;
            int r0 = (16 * m2 + gp) * AIP, r1 = r0 + 8 * AIP;
#pragma unroll
            for (int ks = 0; ks < 4; ks++) {
                int cb = 8 * ks + tg4;
                pa[ks][0] = Au[r0 + cb];
                pa[ks][1] = Au[r1 + cb];
                pa[ks][2] = Au[r0 + cb + 4];
                pa[ks][3] = Au[r1 + cb + 4];
            }
        }
        const int tr0 = 16 * m2 + gp, tr1 = tr0 + 8;
        const bool v0 = tr0 < n, v1 = tr1 < n;
        float* o0 = out + (size_t)Ts[tr0] * H;
        float* o1 = out + (size_t)Ts[tr1] * H;

        for (int pass = 0; pass < 8; pass++) {
            const int bb = pass % 3;
            waitbuf(bb);
            __syncthreads();
            if (pass + 2 < 8) stage_u(pass + 2, (pass + 2) % 3);

            const uint32_t* Ub = (const uint32_t*)(sm + bb * USZ);
            const int hw = 64 * nh;
#pragma unroll 4
            for (int j = 0; j < 8; j++) {
                const int hbb = hw + 8 * j;
                float dd[4] = {0.f, 0.f, 0.f, 0.f};
#pragma unroll
                for (int ks = 0; ks < 4; ks++) {
                    uint32_t b0 = Ub[(8 * ks + tg4) * UPB + hbb + gp];
                    uint32_t b1 = Ub[(8 * ks + tg4 + 4) * UPB + hbb + gp];
                    mma_tf32(dd, pa[ks][0], pa[ks][1], pa[ks][2], pa[ks][3], b0, b1);
                }
                int h0 = pass * 256 + hbb + 2 * tg4;
                if (v0) *(float2*)(o0 + h0) = make_float2(dd[0], dd[1]);
                if (v1) *(float2*)(o1 + h0) = make_float2(dd[2], dd[3]);
            }
        }
    }

    // ================= last-CTA-out cleanup (reset for next replay) =========
    __syncthreads();
    if (tid == 0) {
        __threadfence();
        int v = atomicAdd(&g_done2, 1);
        if (v == (int)gridDim.x - 1) {
#pragma unroll
            for (int i = 0; i < NB; i++) g_count[i] = 0;
            g_done1 = 0;
            g_done2 = 0;
            __threadfence();
        }
    }
}

// ---------------- launch ----------------
extern "C" void kernel_launch(void* const* d_in, const int* in_sizes, int n_in,
                              void* d_out, int out_size) {
    const float* x  = (const float*)d_in[0];
    const float* rw = (const float*)d_in[1];
    const float* dw = (const float*)d_in[2];
    const float* uw = (const float*)d_in[3];
    float* out = (float*)d_out;

    const int smem = SM_FLOATS * sizeof(float); // 110080 B (x2 CTAs <= 228KB/SM)
    cudaFuncSetAttribute(fused_kernel, cudaFuncAttributeMaxDynamicSharedMemorySize, smem);

    fused_kernel<<<GRID, 256, smem>>>(x, rw, dw, uw, out);
}

// round 16
// speedup vs baseline: 1.0141x; 1.0141x over previous
#include <cuda_runtime.h>
#include <math.h>
#include <stdint.h>

// Problem constants
#define H    2048
#define E    8
#define I16  16
#define NTOK 8192
#define NB   64            // bucket ids lo*8+hi (28 valid)
#define TB   32            // tokens per tile (2 CTAs/SM)
#define KC   128           // k-chunk (phase A)
#define NCH  (H / KC)      // 16
#define XP   132           // X/D row pitch (floats)
#define AIP  36            // As pitch over i
#define UPB  264           // Uc row pitch (floats)

// smem layout (float offsets): 3 XD buffers; 3 U buffers overlap XD region
#define XDSZ    (64 * XP)               // one X+D buffer: 8448 floats
#define USZ     (32 * UPB)              // one Uc buffer: 8448 floats
#define AS_OFF  (3 * XDSZ)              // 25344
#define RED_OFF (AS_OFF + TB * AIP)     // 26496
#define SM_FLOATS (RED_OFF + 1024)      // 27520 floats = 110080 B

#define XD_BYTES (64 * 512)             // bulk tx per phase-A chunk
#define U_BYTES  (32 * 1024)            // bulk tx per phase-B pass

// f32x2 helpers (router)
#define FMA2(d, a, b) asm("fma.rn.f32x2 %0, %1, %2, %0;" : "+l"(d) : "l"(a), "l"(b))
#define UNPACK2(lo, hi, d) asm("mov.b64 {%0, %1}, %2;" : "=f"(lo), "=f"(hi) : "l"(d))

__device__ __forceinline__ unsigned su32(const void* p) {
    return (unsigned)__cvta_generic_to_shared(p);
}

// ---- bulk-copy + mbarrier primitives ----
#define MBAR_INIT(addr, cnt) \
    asm volatile("mbarrier.init.shared.b64 [%0], %1;" :: "r"(addr), "r"(cnt) : "memory")
#define MBAR_EXPECT(addr, tx) \
    asm volatile("mbarrier.arrive.expect_tx.shared.b64 _, [%0], %1;" :: "r"(addr), "r"(tx) : "memory")
#define BULK_G2S(dst, src, bytes, mbar) \
    asm volatile("cp.async.bulk.shared::cta.global.mbarrier::complete_tx::bytes [%0], [%1], %2, [%3];" \
                 :: "r"(dst), "l"(src), "r"(bytes), "r"(mbar) : "memory")

__device__ __forceinline__ void mbar_wait(unsigned mbar, unsigned parity) {
    asm volatile(
        "{\n\t"
        ".reg .pred P1;\n\t"
        "LAB_WAIT_%=:\n\t"
        "mbarrier.try_wait.parity.acquire.cta.shared::cta.b64 P1, [%0], %1, 0x989680;\n\t"
        "@P1 bra.uni LAB_DONE_%=;\n\t"
        "bra.uni LAB_WAIT_%=;\n\t"
        "LAB_DONE_%=:\n\t"
        "}"
        :: "r"(mbar), "r"(parity) : "memory");
}

__device__ __forceinline__ uint32_t cvt_tf32(float f) {
    uint32_t r;
    asm("cvt.rna.tf32.f32 %0, %1;" : "=r"(r) : "f"(f));
    return r;
}

__device__ __forceinline__ void mma_tf32(float d[4],
                                         uint32_t a0, uint32_t a1, uint32_t a2, uint32_t a3,
                                         uint32_t b0, uint32_t b1) {
    asm volatile(
        "mma.sync.aligned.m16n8k8.row.col.f32.tf32.tf32.f32 "
        "{%0,%1,%2,%3}, {%4,%5,%6,%7}, {%8,%9}, {%0,%1,%2,%3};"
        : "+f"(d[0]), "+f"(d[1]), "+f"(d[2]), "+f"(d[3])
        : "r"(a0), "r"(a1), "r"(a2), "r"(a3), "r"(b0), "r"(b1));
}

// ---------------- device scratch ----------------
__device__ int      g_count[NB];
__device__ int      g_tok[NB][NTOK];
__device__ float2   g_gate[NB][NTOK];
__device__ float    g_dwc[E * I16 * H];   // dw, tf32-rounded, layout [e][i][h]
__device__ float    g_ut[E * I16 * H];    // uw transposed+rounded: [e][i][h]

// ---------------- K0: prep — zero counts + round dw + transpose uw ----------
__global__ __launch_bounds__(256)
void prep_kernel(const float* __restrict__ dw, const float* __restrict__ uw) {
    if (blockIdx.x == 0 && threadIdx.x < NB) g_count[threadIdx.x] = 0;

    int tid = blockIdx.x * 256 + threadIdx.x;        // 65536 threads, 1 float4 each
    float4 v = ((const float4*)dw)[tid];
    float4 o;
    *(uint32_t*)&o.x = cvt_tf32(v.x);
    *(uint32_t*)&o.y = cvt_tf32(v.y);
    *(uint32_t*)&o.z = cvt_tf32(v.z);
    *(uint32_t*)&o.w = cvt_tf32(v.w);
    ((float4*)g_dwc)[tid] = o;

    float4 u = ((const float4*)uw)[tid];
    int e  = tid >> 13;
    int rm = tid & 8191;
    int h  = rm >> 2;
    int iq = (rm & 3) * 4;
    uint32_t* utb = (uint32_t*)(g_ut + (size_t)(e * I16) * H + h);
    utb[(iq + 0) * H] = cvt_tf32(u.x);
    utb[(iq + 1) * H] = cvt_tf32(u.y);
    utb[(iq + 2) * H] = cvt_tf32(u.z);
    utb[(iq + 3) * H] = cvt_tf32(u.w);
}

// ---------------- K1: router (fp32 f32x2, 4 tok/warp) ----------------
__global__ __launch_bounds__(256)
void router_kernel(const float* __restrict__ x,
                   const float* __restrict__ rw) {
    const int w = threadIdx.x >> 5;
    const int l = threadIdx.x & 31;
    const int t0 = blockIdx.x * 32 + w * 4;

    unsigned long long acc[E][4];
#pragma unroll
    for (int e = 0; e < E; e++)
#pragma unroll
        for (int j = 0; j < 4; j++) acc[e][j] = 0ull;

#pragma unroll 2
    for (int s = 0; s < 16; s++) {
        ulonglong2 xv[4];
#pragma unroll
        for (int j = 0; j < 4; j++)
            xv[j] = ((const ulonglong2*)(x + (size_t)(t0 + j) * H))[l + 32 * s];
#pragma unroll
        for (int e = 0; e < E; e++) {
            ulonglong2 wv = ((const ulonglong2*)(rw + e * H))[l + 32 * s];
#pragma unroll
            for (int j = 0; j < 4; j++) {
                FMA2(acc[e][j], xv[j].x, wv.x);
                FMA2(acc[e][j], xv[j].y, wv.y);
            }
        }
    }

    float lg[E];
#pragma unroll
    for (int e = 0; e < E; e++) {
#pragma unroll
        for (int j = 0; j < 4; j++) {
            float s0, s1;
            UNPACK2(s0, s1, acc[e][j]);
            float v = s0 + s1;
#pragma unroll
            for (int o = 16; o > 0; o >>= 1) v += __shfl_xor_sync(0xffffffffu, v, o);
            if (l == j) lg[e] = v;
        }
    }

    if (l < 4) {
        int t = t0 + l;
        float m = lg[0];
#pragma unroll
        for (int e = 1; e < E; e++) m = fmaxf(m, lg[e]);
        float wgt[E]; float ssum = 0.f;
#pragma unroll
        for (int e = 0; e < E; e++) { wgt[e] = __expf(lg[e] - m); ssum += wgt[e]; }
        float inv = 1.f / ssum;

        int i1 = 0; float v1 = wgt[0];
#pragma unroll
        for (int e = 1; e < E; e++) if (wgt[e] > v1) { v1 = wgt[e]; i1 = e; }
        int i2 = -1; float v2 = -1.f;
#pragma unroll
        for (int e = 0; e < E; e++)
            if (e != i1 && wgt[e] > v2) { v2 = wgt[e]; i2 = e; }

        float g1 = v1 * inv, g2 = v2 * inv;
        int lo, hi; float glo, ghi;
        if (i1 < i2) { lo = i1; hi = i2; glo = g1; ghi = g2; }
        else         { lo = i2; hi = i1; glo = g2; ghi = g1; }
        int p = lo * 8 + hi;
        int slot = atomicAdd(&g_count[p], 1);
        g_tok[p][slot]  = t;
        g_gate[p][slot] = make_float2(glo, ghi);
    }
}

// ---------------- K2: expert compute (R14 verbatim: TB=32, 2 CTAs/SM) -------
__global__ __launch_bounds__(256, 2)
void expert_kernel(const float* __restrict__ x,
                   float* __restrict__ out) {
    extern __shared__ float sm[];
    float* As  = sm + AS_OFF;
    float* Red = sm + RED_OFF;

    __shared__ int    pref[NB + 1];
    __shared__ int    Ts[TB];
    __shared__ float2 Gs[TB];
    __shared__ __align__(8) unsigned long long mbars[3];

    const int tid = threadIdx.x;
    const int w = tid >> 5;
    const int l = tid & 31;
    const int gp  = l >> 2;          // group id (0..7)
    const int tg4 = l & 3;           // thread in group
    // phase A warp tile
    const int kg = w >> 2;           // split-K group (0..1)
    const int wl = w & 3;
    const int mw = wl & 1;           // token block (16 tok)
    const int nw = wl >> 1;          // i block (16 i)
    // phase B warp tile
    const int m2 = w & 1;            // token half (16 tok)
    const int nh = w >> 1;           // h quarter (64 h)

    const unsigned mb0 = su32(&mbars[0]);
    const unsigned mb1 = su32(&mbars[1]);
    const unsigned mb2 = su32(&mbars[2]);
    int ph0 = 0, ph1 = 0, ph2 = 0;

    if (tid == 0) { MBAR_INIT(mb0, 1); MBAR_INIT(mb1, 1); MBAR_INIT(mb2, 1); }

    auto waitbuf = [&](int bb) {
        if (bb == 0)      { mbar_wait(mb0, ph0); ph0 ^= 1; }
        else if (bb == 1) { mbar_wait(mb1, ph1); ph1 ^= 1; }
        else              { mbar_wait(mb2, ph2); ph2 ^= 1; }
    };

    // flat tile prefix
    if (tid < NB) {
        int lo_ = tid >> 3, hi_ = tid & 7;
        pref[tid + 1] = (lo_ < hi_) ? (g_count[tid] + TB - 1) / TB : 0;
    }
    __syncthreads();
    if (tid == 0) {
        int s = 0;
        pref[0] = 0;
        for (int i = 1; i <= NB; i++) { s += pref[i]; pref[i] = s; }
    }
    __syncthreads();
    const int ntiles = pref[NB];

    for (int ft = blockIdx.x; ft < ntiles; ft += gridDim.x) {
        int a = 0, b = NB;
        while (b - a > 1) { int mM = (a + b) >> 1; if (pref[mM] <= ft) a = mM; else b = mM; }
        const int p  = a;
        const int lo = p >> 3, hi = p & 7;
        const int cnt  = g_count[p];
        const int base = (ft - pref[p]) * TB;
        const int n    = min(TB, cnt - base);

        __syncthreads();             // prev tile fully done with smem
        if (tid < TB) {
            int src = base + ((tid < n) ? tid : 0);
            Ts[tid] = g_tok[p][src];
            float2 gg = g_gate[p][src];
            if (tid >= n) gg = make_float2(0.f, 0.f);
            Gs[tid] = gg;
        }
        __syncthreads();             // Ts visible to staging threads

        // ---------------- Phase A ----------------
        float d[2][4];
#pragma unroll
        for (int t = 0; t < 2; t++)
#pragma unroll
            for (int q = 0; q < 4; q++) d[t][q] = 0.f;

        auto stage = [&](int c, int bb) {
            unsigned mb = (bb == 0) ? mb0 : (bb == 1) ? mb1 : mb2;
            if (tid == 0) MBAR_EXPECT(mb, XD_BYTES);
            if (tid < 32) {
                unsigned dst = su32(sm + bb * XDSZ + tid * XP);
                BULK_G2S(dst, x + (size_t)Ts[tid] * H + c * KC, 512, mb);
            } else if (tid < 64) {
                int r = tid - 32;
                int e = (r < 16) ? lo : hi;
                unsigned dst = su32(sm + bb * XDSZ + (32 + r) * XP);
                BULK_G2S(dst, g_dwc + (size_t)(e * I16 + (r & 15)) * H + c * KC, 512, mb);
            }
        };

        stage(0, 0);
        stage(1, 1);

        const int xr0 = (16 * mw + gp) * XP;
        const int xr1 = xr0 + 8 * XP;
        const int dr0 = (32 + 16 * nw + gp) * XP;    // D rows live at +32
        const int dr1 = dr0 + 8 * XP;

        for (int c = 0; c < NCH; c++) {
            const int bb = c % 3;
            waitbuf(bb);
            __syncthreads();         // readers of chunk c-1 (buffer (c+2)%3) done
            if (c + 2 < NCH) stage(c + 2, (c + 2) % 3);

            const float*    Xb = sm + bb * XDSZ;
            const uint32_t* Db = (const uint32_t*)Xb;
#pragma unroll
            for (int si = 0; si < 8; si++) {
                const int ca = 8 * (8 * kg + si) + tg4;
                uint32_t a0 = cvt_tf32(Xb[xr0 + ca]);
                uint32_t a1 = cvt_tf32(Xb[xr1 + ca]);
                uint32_t a2 = cvt_tf32(Xb[xr0 + ca + 4]);
                uint32_t a3 = cvt_tf32(Xb[xr1 + ca + 4]);
                uint32_t b00 = Db[dr0 + ca];
                uint32_t b01 = Db[dr0 + ca + 4];
                uint32_t b10 = Db[dr1 + ca];
                uint32_t b11 = Db[dr1 + ca + 4];
                mma_tf32(d[0], a0, a1, a2, a3, b00, b01);
                mma_tf32(d[1], a0, a1, a2, a3, b10, b11);
            }
        }

        // split-K reduce: kg==1 writes partials to Red
        if (kg == 1) {
            float* rp = Red + wl * 256 + l * 8;
            *(float4*)(rp)     = make_float4(d[0][0], d[0][1], d[0][2], d[0][3]);
            *(float4*)(rp + 4) = make_float4(d[1][0], d[1][1], d[1][2], d[1][3]);
        }
        __syncthreads();

        // epilogue (kg==0): add partial, silu + gate + tf32-round -> As[tok][i]
        if (kg == 0) {
            const float* rp = Red + wl * 256 + l * 8;
            int r0 = 16 * mw + gp, r1 = r0 + 8;
            float2 gg0 = Gs[r0], gg1 = Gs[r1];
            float gt0 = nw ? gg0.y : gg0.x;
            float gt1 = nw ? gg1.y : gg1.x;
#pragma unroll
            for (int t = 0; t < 2; t++) {
                int cbase = 16 * nw + 8 * t + 2 * tg4;
#pragma unroll
                for (int q = 0; q < 4; q++) {
                    float hv = d[t][q] + rp[t * 4 + q];
                    float sig = 1.f / (1.f + __expf(-hv));
                    float gate = (q < 2) ? gt0 : gt1;
                    float val = gate * hv * sig;
                    int row = (q < 2) ? r0 : r1;
                    int col = cbase + (q & 1);
                    *(uint32_t*)&As[row * AIP + col] = cvt_tf32(val);
                }
            }
        }
        __syncthreads();             // As ready; XD region free for Uc

        // ---------------- Phase B ----------------
        auto stage_u = [&](int pp, int bb) {
            unsigned mb = (bb == 0) ? mb0 : (bb == 1) ? mb1 : mb2;
            if (tid == 0) MBAR_EXPECT(mb, U_BYTES);
            if (tid < 32) {
                int e = (tid < 16) ? lo : hi;
                unsigned dst = su32(sm + bb * USZ + tid * UPB);
                BULK_G2S(dst, g_ut + (size_t)(e * I16 + (tid & 15)) * H + pp * 256, 1024, mb);
            }
        };

        stage_u(0, 0);
        stage_u(1, 1);

        uint32_t pa[4][4];
        {
            const uint32_t* Au = (const uint32_t*)As;
            int r0 = (16 * m2 + gp) * AIP, r1 = r0 + 8 * AIP;
#pragma unroll
            for (int ks = 0; ks < 4; ks++) {
                int cb = 8 * ks + tg4;
                pa[ks][0] = Au[r0 + cb];
                pa[ks][1] = Au[r1 + cb];
                pa[ks][2] = Au[r0 + cb + 4];
                pa[ks][3] = Au[r1 + cb + 4];
            }
        }
        const int tr0 = 16 * m2 + gp, tr1 = tr0 + 8;
        const bool v0 = tr0 < n, v1 = tr1 < n;
        float* o0 = out + (size_t)Ts[tr0] * H;
        float* o1 = out + (size_t)Ts[tr1] * H;

        for (int pass = 0; pass < 8; pass++) {
            const int bb = pass % 3;
            waitbuf(bb);
            __syncthreads();         // readers of pass-1 (buffer (pass+2)%3) done
            if (pass + 2 < 8) stage_u(pass + 2, (pass + 2) % 3);

            const uint32_t* Ub = (const uint32_t*)(sm + bb * USZ);
            const int hw = 64 * nh;
#pragma unroll 4
            for (int j = 0; j < 8; j++) {
                const int hbb = hw + 8 * j;
                float dd[4] = {0.f, 0.f, 0.f, 0.f};
#pragma unroll
                for (int ks = 0; ks < 4; ks++) {
                    uint32_t b0 = Ub[(8 * ks + tg4) * UPB + hbb + gp];
                    uint32_t b1 = Ub[(8 * ks + tg4 + 4) * UPB + hbb + gp];
                    mma_tf32(dd, pa[ks][0], pa[ks][1], pa[ks][2], pa[ks][3], b0, b1);
                }
                int h0 = pass * 256 + hbb + 2 * tg4;
                if (v0) *(float2*)(o0 + h0) = make_float2(dd[0], dd[1]);
                if (v1) *(float2*)(o1 + h0) = make_float2(dd[2], dd[3]);
            }
        }
    }
}

// ---------------- launch ----------------
extern "C" void kernel_launch(void* const* d_in, const int* in_sizes, int n_in,
                              void* d_out, int out_size) {
    const float* x  = (const float*)d_in[0];
    const float* rw = (const float*)d_in[1];
    const float* dw = (const float*)d_in[2];
    const float* uw = (const float*)d_in[3];
    float* out = (float*)d_out;

    const int ek_smem = SM_FLOATS * sizeof(float); // 110080 B (x2 CTAs <= 228KB/SM)
    cudaFuncSetAttribute(expert_kernel, cudaFuncAttributeMaxDynamicSharedMemorySize, ek_smem);

    prep_kernel<<<256, 256>>>(dw, uw);
    router_kernel<<<NTOK / 32, 256>>>(x, rw);
    expert_kernel<<<296, 256, ek_smem>>>(x, out);
}

// round 17
// speedup vs baseline: 1.0847x; 1.0696x over previous
#include <cuda_runtime.h>
#include <math.h>
#include <stdint.h>

// Problem constants
#define H    2048
#define E    8
#define I16  16
#define NTOK 8192
#define NB   64            // bucket ids lo*8+hi (28 valid)
#define TB   64            // tokens per tile
#define KC   128           // k-chunk (phase A)
#define NCH  (H / KC)      // 16
#define XP   132           // X/D row pitch (floats)
#define AIP  36            // As pitch over i
#define UPB  264           // Uc row pitch (floats)

// smem layout (float offsets)
#define XDSZ   (96 * XP)               // one X+D buffer: 12672 floats
#define USZ    (32 * UPB)              // one Uc buffer: 8448 floats (overlaps XD region)
#define AS_OFF (2 * XDSZ)              // 25344
#define SM_FLOATS (AS_OFF + TB * AIP)  // 27648 floats = 110592 B

// f32x2 helpers (router)
#define FMA2(d, a, b) asm("fma.rn.f32x2 %0, %1, %2, %0;" : "+l"(d) : "l"(a), "l"(b))
#define UNPACK2(lo, hi, d) asm("mov.b64 {%0, %1}, %2;" : "=f"(lo), "=f"(hi) : "l"(d))

__device__ __forceinline__ unsigned su32(const void* p) {
    return (unsigned)__cvta_generic_to_shared(p);
}
#define CP16(dst, src) asm volatile("cp.async.cg.shared.global [%0], [%1], 16;" :: "r"(dst), "l"(src))
#define CP_COMMIT()    asm volatile("cp.async.commit_group;" ::: "memory")
#define CP_WAIT0()     asm volatile("cp.async.wait_group 0;" ::: "memory")

__device__ __forceinline__ uint32_t cvt_tf32(float f) {
    uint32_t r;
    asm("cvt.rna.tf32.f32 %0, %1;" : "=r"(r) : "f"(f));
    return r;
}

__device__ __forceinline__ void mma_tf32(float d[4],
                                         uint32_t a0, uint32_t a1, uint32_t a2, uint32_t a3,
                                         uint32_t b0, uint32_t b1) {
    asm volatile(
        "mma.sync.aligned.m16n8k8.row.col.f32.tf32.tf32.f32 "
        "{%0,%1,%2,%3}, {%4,%5,%6,%7}, {%8,%9}, {%0,%1,%2,%3};"
        : "+f"(d[0]), "+f"(d[1]), "+f"(d[2]), "+f"(d[3])
        : "r"(a0), "r"(a1), "r"(a2), "r"(a3), "r"(b0), "r"(b1));
}

// ---------------- device scratch ----------------
__device__ int      g_count[NB];
__device__ int      g_tok[NB][NTOK];
__device__ float2   g_gate[NB][NTOK];
__device__ float    g_dwc[E * I16 * H];   // dw, tf32-rounded, same layout [e][i][h]
__device__ float    g_ut[E * I16 * H];    // uw transposed+rounded: [e][i][h]

// ---------------- K0: prep — zero counts, round dw, transpose+round uw ----
__global__ __launch_bounds__(256)
void prep_kernel(const float* __restrict__ dw, const float* __restrict__ uw) {
    if (blockIdx.x == 0 && threadIdx.x < NB) g_count[threadIdx.x] = 0;

    int tid = blockIdx.x * 256 + threadIdx.x;        // 65536 threads, 1 float4 each
    // dwc (layout preserved)
    float4 v = ((const float4*)dw)[tid];
    float4 o;
    *(uint32_t*)&o.x = cvt_tf32(v.x);
    *(uint32_t*)&o.y = cvt_tf32(v.y);
    *(uint32_t*)&o.z = cvt_tf32(v.z);
    *(uint32_t*)&o.w = cvt_tf32(v.w);
    ((float4*)g_dwc)[tid] = o;
    // ut: src uw[e][h][i] (float4 = 4 consecutive i) -> g_ut[e][i][h]
    float4 u = ((const float4*)uw)[tid];
    int e  = tid >> 13;            // H*I16/4 = 8192 float4 per expert
    int rm = tid & 8191;
    int h  = rm >> 2;
    int iq = (rm & 3) * 4;
    uint32_t* utb = (uint32_t*)(g_ut + (size_t)(e * I16) * H + h);
    utb[(iq + 0) * H] = cvt_tf32(u.x);
    utb[(iq + 1) * H] = cvt_tf32(u.y);
    utb[(iq + 2) * H] = cvt_tf32(u.z);
    utb[(iq + 3) * H] = cvt_tf32(u.w);
}

// ---------------- K1: router (fp32 f32x2, 4 tok/warp) ----------------
__global__ __launch_bounds__(256)
void router_kernel(const float* __restrict__ x,
                   const float* __restrict__ rw) {
    const int w = threadIdx.x >> 5;
    const int l = threadIdx.x & 31;
    const int t0 = blockIdx.x * 32 + w * 4;

    unsigned long long acc[E][4];
#pragma unroll
    for (int e = 0; e < E; e++)
#pragma unroll
        for (int j = 0; j < 4; j++) acc[e][j] = 0ull;

#pragma unroll 2
    for (int s = 0; s < 16; s++) {
        ulonglong2 xv[4];
#pragma unroll
        for (int j = 0; j < 4; j++)
            xv[j] = ((const ulonglong2*)(x + (size_t)(t0 + j) * H))[l + 32 * s];
#pragma unroll
        for (int e = 0; e < E; e++) {
            ulonglong2 wv = ((const ulonglong2*)(rw + e * H))[l + 32 * s];
#pragma unroll
            for (int j = 0; j < 4; j++) {
                FMA2(acc[e][j], xv[j].x, wv.x);
                FMA2(acc[e][j], xv[j].y, wv.y);
            }
        }
    }

    float lg[E];
#pragma unroll
    for (int e = 0; e < E; e++) {
#pragma unroll
        for (int j = 0; j < 4; j++) {
            float s0, s1;
            UNPACK2(s0, s1, acc[e][j]);
            float v = s0 + s1;
#pragma unroll
            for (int o = 16; o > 0; o >>= 1) v += __shfl_xor_sync(0xffffffffu, v, o);
            if (l == j) lg[e] = v;
        }
    }

    if (l < 4) {
        int t = t0 + l;
        float m = lg[0];
#pragma unroll
        for (int e = 1; e < E; e++) m = fmaxf(m, lg[e]);
        float wgt[E]; float ssum = 0.f;
#pragma unroll
        for (int e = 0; e < E; e++) { wgt[e] = __expf(lg[e] - m); ssum += wgt[e]; }
        float inv = 1.f / ssum;

        int i1 = 0; float v1 = wgt[0];
#pragma unroll
        for (int e = 1; e < E; e++) if (wgt[e] > v1) { v1 = wgt[e]; i1 = e; }
        int i2 = -1; float v2 = -1.f;
#pragma unroll
        for (int e = 0; e < E; e++)
            if (e != i1 && wgt[e] > v2) { v2 = wgt[e]; i2 = e; }

        float g1 = v1 * inv, g2 = v2 * inv;
        int lo, hi; float glo, ghi;
        if (i1 < i2) { lo = i1; hi = i2; glo = g1; ghi = g2; }
        else         { lo = i2; hi = i1; glo = g2; ghi = g1; }
        int p = lo * 8 + hi;
        int slot = atomicAdd(&g_count[p], 1);
        g_tok[p][slot]  = t;
        g_gate[p][slot] = make_float2(glo, ghi);
    }
}

// ---------------- K2: expert compute (R10 verbatim) ----------------
// Phase A: C[64,32] = X[64,2048]·D[32,2048]^T. Warp = 16 tok x 16 i,
//   full K, mma.m16n8k8.tf32; X/D chunks cp.async double-buffered.
// Phase B: out[64,2048] = As[64,32]·Ut[32,2048]; Uc[32][256] per pass,
//   double-buffered; d regs stored directly to gmem.
__global__ __launch_bounds__(256, 1)
void expert_kernel(const float* __restrict__ x,
                   float* __restrict__ out) {
    extern __shared__ float sm[];
    float* As = sm + AS_OFF;

    __shared__ int    pref[NB + 1];
    __shared__ int    Ts[TB];
    __shared__ float2 Gs[TB];

    const int tid = threadIdx.x;
    const int w = tid >> 5;
    const int l = tid & 31;
    const int gp  = l >> 2;          // group id (0..7)
    const int tg4 = l & 3;           // thread in group
    // phase A warp tile
    const int mw = w & 3;            // token block (16 tok)
    const int nw = w >> 2;           // i block (16 i)
    // phase B warp tile
    const int m2 = w & 3;            // token block
    const int nh = w >> 2;           // h half within pass (128 h)

    // flat tile prefix
    if (tid < NB) {
        int lo_ = tid >> 3, hi_ = tid & 7;
        pref[tid + 1] = (lo_ < hi_) ? (g_count[tid] + TB - 1) / TB : 0;
    }
    __syncthreads();
    if (tid == 0) {
        int s = 0;
        pref[0] = 0;
        for (int i = 1; i <= NB; i++) { s += pref[i]; pref[i] = s; }
    }
    __syncthreads();
    const int ntiles = pref[NB];

    for (int ft = blockIdx.x; ft < ntiles; ft += gridDim.x) {
        int a = 0, b = NB;
        while (b - a > 1) { int mM = (a + b) >> 1; if (pref[mM] <= ft) a = mM; else b = mM; }
        const int p  = a;
        const int lo = p >> 3, hi = p & 7;
        const int cnt  = g_count[p];
        const int base = (ft - pref[p]) * TB;
        const int n    = min(TB, cnt - base);

        __syncthreads();             // prev tile fully done with smem
        if (tid < TB) {
            int src = base + ((tid < n) ? tid : 0);
            Ts[tid] = g_tok[p][src];
            float2 gg = g_gate[p][src];
            if (tid >= n) gg = make_float2(0.f, 0.f);
            Gs[tid] = gg;
        }
        __syncthreads();

        // ================= Phase A =================
        float d[2][4];
#pragma unroll
        for (int t = 0; t < 2; t++)
#pragma unroll
            for (int q = 0; q < 4; q++) d[t][q] = 0.f;

        auto stage = [&](int c, int bb) {
            float* dst = sm + bb * XDSZ;
            int koff = c * KC;
#pragma unroll
            for (int j = 0; j < 8; j++) {
                int idx = tid + 256 * j, r = idx >> 5, q = idx & 31;
                CP16(su32(dst + r * XP + 4 * q),
                     x + (size_t)Ts[r] * H + koff + 4 * q);
            }
#pragma unroll
            for (int j = 0; j < 4; j++) {
                int idx = tid + 256 * j, r = idx >> 5, q = idx & 31;
                int e = (r < 16) ? lo : hi;
                CP16(su32(dst + (64 + r) * XP + 4 * q),
                     g_dwc + (size_t)(e * I16 + (r & 15)) * H + koff + 4 * q);
            }
        };

        stage(0, 0); CP_COMMIT();

        const int xr0 = (16 * mw + gp) * XP;
        const int xr1 = xr0 + 8 * XP;
        const int dr0 = (64 + 16 * nw + gp) * XP;      // D rows live at +64
        const int dr1 = dr0 + 8 * XP;

        for (int c = 0; c < NCH; c++) {
            CP_WAIT0();
            __syncthreads();         // chunk c visible; buf (c+1)&1 free
            if (c + 1 < NCH) { stage(c + 1, (c + 1) & 1); CP_COMMIT(); }

            const float*    Xb = sm + (c & 1) * XDSZ;
            const uint32_t* Db = (const uint32_t*)Xb;
#pragma unroll
            for (int s = 0; s < 16; s++) {
                const int ca = 8 * s + tg4;
                uint32_t a0 = cvt_tf32(Xb[xr0 + ca]);
                uint32_t a1 = cvt_tf32(Xb[xr1 + ca]);
                uint32_t a2 = cvt_tf32(Xb[xr0 + ca + 4]);
                uint32_t a3 = cvt_tf32(Xb[xr1 + ca + 4]);
                uint32_t b00 = Db[dr0 + ca];
                uint32_t b01 = Db[dr0 + ca + 4];
                uint32_t b10 = Db[dr1 + ca];
                uint32_t b11 = Db[dr1 + ca + 4];
                mma_tf32(d[0], a0, a1, a2, a3, b00, b01);
                mma_tf32(d[1], a0, a1, a2, a3, b10, b11);
            }
        }

        // epilogue: silu + gate + tf32-round -> As[tok][i]
        {
            int r0 = 16 * mw + gp, r1 = r0 + 8;
            float2 gg0 = Gs[r0], gg1 = Gs[r1];
            float gt0 = nw ? gg0.y : gg0.x;
            float gt1 = nw ? gg1.y : gg1.x;
#pragma unroll
            for (int t = 0; t < 2; t++) {
                int cbase = 16 * nw + 8 * t + 2 * tg4;
#pragma unroll
                for (int q = 0; q < 4; q++) {
                    float hv = d[t][q];
                    float sig = 1.f / (1.f + __expf(-hv));
                    float gate = (q < 2) ? gt0 : gt1;
                    float val = gate * hv * sig;
                    int row = (q < 2) ? r0 : r1;
                    int col = cbase + (q & 1);
                    *(uint32_t*)&As[row * AIP + col] = cvt_tf32(val);
                }
            }
        }
        __syncthreads();             // As ready; XD region free for Uc

        // ================= Phase B =================
        auto stage_u = [&](int pp, int bb) {
            float* dst = sm + bb * USZ;
#pragma unroll
            for (int j = 0; j < 8; j++) {
                int idx = tid + 256 * j, r = idx >> 6, q = idx & 63;
                int e = (r < 16) ? lo : hi;
                CP16(su32(dst + r * UPB + 4 * q),
                     g_ut + (size_t)(e * I16 + (r & 15)) * H + pp * 256 + 4 * q);
            }
        };

        stage_u(0, 0); CP_COMMIT();

        // hoist A fragments (constant across passes) and out pointers
        uint32_t pa[4][4];
        {
            const uint32_t* Au = (const uint32_t*)As;
            int r0 = (16 * m2 + gp) * AIP, r1 = r0 + 8 * AIP;
#pragma unroll
            for (int ks = 0; ks < 4; ks++) {
                int cb = 8 * ks + tg4;
                pa[ks][0] = Au[r0 + cb];
                pa[ks][1] = Au[r1 + cb];
                pa[ks][2] = Au[r0 + cb + 4];
                pa[ks][3] = Au[r1 + cb + 4];
            }
        }
        const int tr0 = 16 * m2 + gp, tr1 = tr0 + 8;
        const bool v0 = tr0 < n, v1 = tr1 < n;
        float* o0 = out + (size_t)Ts[tr0] * H;
        float* o1 = out + (size_t)Ts[tr1] * H;

        for (int pass = 0; pass < 8; pass++) {
            CP_WAIT0();
            __syncthreads();         // Uc pass visible; other buffer free
            if (pass + 1 < 8) { stage_u(pass + 1, (pass + 1) & 1); CP_COMMIT(); }

            const uint32_t* Ub = (const uint32_t*)(sm + (pass & 1) * USZ);
            const int hw = 128 * nh;
#pragma unroll 4
            for (int j = 0; j < 16; j++) {
                const int hbb = hw + 8 * j;
                float dd[4] = {0.f, 0.f, 0.f, 0.f};
#pragma unroll
                for (int ks = 0; ks < 4; ks++) {
                    uint32_t b0 = Ub[(8 * ks + tg4) * UPB + hbb + gp];
                    uint32_t b1 = Ub[(8 * ks + tg4 + 4) * UPB + hbb + gp];
                    mma_tf32(dd, pa[ks][0], pa[ks][1], pa[ks][2], pa[ks][3], b0, b1);
                }
                int h0 = pass * 256 + hbb + 2 * tg4;
                if (v0) *(float2*)(o0 + h0) = make_float2(dd[0], dd[1]);
                if (v1) *(float2*)(o1 + h0) = make_float2(dd[2], dd[3]);
            }
        }
    }
}

// ---------------- launch ----------------
extern "C" void kernel_launch(void* const* d_in, const int* in_sizes, int n_in,
                              void* d_out, int out_size) {
    const float* x  = (const float*)d_in[0];
    const float* rw = (const float*)d_in[1];
    const float* dw = (const float*)d_in[2];
    const float* uw = (const float*)d_in[3];
    float* out = (float*)d_out;

    const int ek_smem = SM_FLOATS * sizeof(float); // 110592 B
    cudaFuncSetAttribute(expert_kernel, cudaFuncAttributeMaxDynamicSharedMemorySize, ek_smem);

    prep_kernel<<<256, 256>>>(dw, uw);
    router_kernel<<<NTOK / 32, 256>>>(x, rw);
    expert_kernel<<<148, 256, ek_smem>>>(x, out);
}